// round 1
// baseline (speedup 1.0000x reference)
#include <cuda_runtime.h>
#include <cuda_bf16.h>

// Problem constants
#define BB 8
#define NN 128
#define LL 4096
#define DD 1024
#define HH 16
#define DH 64
#define BH (BB*HH)          // 128
#define LTILES (LL/32)      // 128 tiles of 32 l-columns for softmax

// ---------------- scratch (device globals; allocation-free) ----------------
__device__ float g_Qp[BB*NN*DD];            // 4 MB
__device__ float g_Kp[BB*LL*DD];            // 128 MB
__device__ float g_Vp[BB*LL*DD];            // 128 MB
__device__ float g_S [BH*NN*LL];            // 256 MB  (scores, overwritten by P)
__device__ float g_rowpart[BH*LTILES*NN];   // 8 MB
__device__ float g_rowsum[BH*NN];           // 64 KB
__device__ float g_O [BB*NN*DD];            // 4 MB

// ---------------- generic NT GEMM: C[m,n] = alpha * sum_k A[m,k]*B[n,k] ----
// 128x128 tile, BK=16, 256 threads, 8x8 per thread (2x2 quadrants of 4x4).
#define BM 128
#define BN 128
#define BK 16
#define PAD 4

__global__ void __launch_bounds__(256, 2)
gemm_nt(const float* __restrict__ Ag, const float* __restrict__ Bg,
        float* __restrict__ Cg,
        int K, int lda, int ldb, int ldc,
        long sAb, long sAh, long sBb, long sBh, long sCb, long sCh,
        int ZH, float alpha)
{
    __shared__ float As[BK][BM + PAD];
    __shared__ float Bs[BK][BN + PAD];

    const int z  = blockIdx.z;
    const int zb = z / ZH;
    const int zh = z % ZH;
    const float* A = Ag + zb * sAb + zh * sAh;
    const float* Bp = Bg + zb * sBb + zh * sBh;
    float* C = Cg + zb * sCb + zh * sCh;

    const int m0 = blockIdx.y * BM;
    const int n0 = blockIdx.x * BN;
    const int tid = threadIdx.x;

    const int lRow = tid >> 2;         // 0..63
    const int lCol = (tid & 3) * 4;    // 0,4,8,12

    const int tx = tid & 15;
    const int ty = tid >> 4;

    float acc[8][8];
#pragma unroll
    for (int i = 0; i < 8; i++)
#pragma unroll
        for (int j = 0; j < 8; j++) acc[i][j] = 0.f;

    for (int k0 = 0; k0 < K; k0 += BK) {
#pragma unroll
        for (int rr = 0; rr < 2; rr++) {
            int m = lRow + rr * 64;
            float4 v = *reinterpret_cast<const float4*>(
                &A[(long)(m0 + m) * lda + k0 + lCol]);
            As[lCol + 0][m] = v.x;
            As[lCol + 1][m] = v.y;
            As[lCol + 2][m] = v.z;
            As[lCol + 3][m] = v.w;
        }
#pragma unroll
        for (int rr = 0; rr < 2; rr++) {
            int n = lRow + rr * 64;
            float4 v = *reinterpret_cast<const float4*>(
                &Bp[(long)(n0 + n) * ldb + k0 + lCol]);
            Bs[lCol + 0][n] = v.x;
            Bs[lCol + 1][n] = v.y;
            Bs[lCol + 2][n] = v.z;
            Bs[lCol + 3][n] = v.w;
        }
        __syncthreads();

#pragma unroll
        for (int kk = 0; kk < BK; kk++) {
            float a[8], b[8];
            float4 t;
            t = *reinterpret_cast<const float4*>(&As[kk][ty * 4]);
            a[0]=t.x; a[1]=t.y; a[2]=t.z; a[3]=t.w;
            t = *reinterpret_cast<const float4*>(&As[kk][64 + ty * 4]);
            a[4]=t.x; a[5]=t.y; a[6]=t.z; a[7]=t.w;
            t = *reinterpret_cast<const float4*>(&Bs[kk][tx * 4]);
            b[0]=t.x; b[1]=t.y; b[2]=t.z; b[3]=t.w;
            t = *reinterpret_cast<const float4*>(&Bs[kk][64 + tx * 4]);
            b[4]=t.x; b[5]=t.y; b[6]=t.z; b[7]=t.w;
#pragma unroll
            for (int i = 0; i < 8; i++)
#pragma unroll
                for (int j = 0; j < 8; j++)
                    acc[i][j] += a[i] * b[j];
        }
        __syncthreads();
    }

#pragma unroll
    for (int i = 0; i < 8; i++) {
        int m = m0 + ((i < 4) ? (ty * 4 + i) : (64 + ty * 4 + (i - 4)));
#pragma unroll
        for (int jg = 0; jg < 2; jg++) {
            int n = n0 + ((jg == 0) ? (tx * 4) : (64 + tx * 4));
            float4 v;
            v.x = acc[i][jg*4+0] * alpha;
            v.y = acc[i][jg*4+1] * alpha;
            v.z = acc[i][jg*4+2] * alpha;
            v.w = acc[i][jg*4+3] * alpha;
            *reinterpret_cast<float4*>(&C[(long)m * ldc + n]) = v;
        }
    }
}

// ---------------- inverted softmax (over the query axis n), fused ----------
// For each (bh) slab S[n=128][l=4096]:
//   E = exp(S - colmax_n), P = E / colsum_n  (written back into S)
//   partial row sums (over 32 l per block) go to g_rowpart (no atomics).
__global__ void __launch_bounds__(256)
softmax_inv_kernel(float* __restrict__ S, float* __restrict__ rowpart)
{
    const int bh   = blockIdx.y;
    const int lane = threadIdx.x & 31;
    const int g    = threadIdx.x >> 5;          // warp 0..7
    const int l    = blockIdx.x * 32 + lane;

    float* Sp = S + (long)bh * NN * LL;

    float s[16];
#pragma unroll
    for (int r = 0; r < 16; r++) {
        int n = g + r * 8;
        s[r] = Sp[(long)n * LL + l];
    }

    __shared__ float red[8][32];

    // column max over n
    float m = s[0];
#pragma unroll
    for (int r = 1; r < 16; r++) m = fmaxf(m, s[r]);
    red[g][lane] = m;
    __syncthreads();
    float cm = red[0][lane];
#pragma unroll
    for (int i = 1; i < 8; i++) cm = fmaxf(cm, red[i][lane]);
    __syncthreads();

    // exp and column sum
    float sum = 0.f;
#pragma unroll
    for (int r = 0; r < 16; r++) {
        s[r] = __expf(s[r] - cm);
        sum += s[r];
    }
    red[g][lane] = sum;
    __syncthreads();
    float cs = 0.f;
#pragma unroll
    for (int i = 0; i < 8; i++) cs += red[i][lane];
    float inv = 1.f / cs;

    // write P, accumulate row partials (warp-reduce over the 32 l-lanes)
#pragma unroll
    for (int r = 0; r < 16; r++) {
        int n = g + r * 8;
        float p = s[r] * inv;
        s[r] = p;
        Sp[(long)n * LL + l] = p;
    }
#pragma unroll
    for (int r = 0; r < 16; r++) {
        float v = s[r];
#pragma unroll
        for (int off = 16; off > 0; off >>= 1)
            v += __shfl_xor_sync(0xffffffffu, v, off);
        if (lane == 0)
            rowpart[((long)bh * LTILES + blockIdx.x) * NN + (g + r * 8)] = v;
    }
}

// ---------------- rowsum reduce over the 128 l-tiles ------------------------
__global__ void rowsum_kernel(const float* __restrict__ rowpart,
                              float* __restrict__ rowsum)
{
    int idx = blockIdx.x * blockDim.x + threadIdx.x;   // bh*128 + n
    if (idx >= BH * NN) return;
    int bh = idx >> 7;
    int n  = idx & 127;
    const float* p = rowpart + (long)bh * LTILES * NN + n;
    float s = 0.f;
#pragma unroll 8
    for (int t = 0; t < LTILES; t++) s += p[(long)t * NN];
    rowsum[idx] = s;
}

// ---------------- AV: O[b,n,h*64+c] = (sum_l P[n,l] V[b,l,h*64+c]) / rowsum -
__global__ void __launch_bounds__(256)
av_kernel(const float* __restrict__ P, const float* __restrict__ V,
          const float* __restrict__ rowsum, float* __restrict__ O)
{
    const int bh = blockIdx.x;
    const int b  = bh >> 4;
    const int h  = bh & 15;
    const float* Pp = P + (long)bh * NN * LL;
    const float* Vp = V + (long)b * LL * DD + h * DH;

    __shared__ float Ps[32][BM + PAD];   // [kk][n]
    __shared__ float Vs[32][DH + 4];     // [kk][c]

    const int tid = threadIdx.x;
    const int tx  = tid & 15;            // cols (c): tx*4 .. +3
    const int ty  = tid >> 4;            // rows (n): ty*4 and 64+ty*4

    float acc[8][4];
#pragma unroll
    for (int i = 0; i < 8; i++)
#pragma unroll
        for (int j = 0; j < 4; j++) acc[i][j] = 0.f;

    for (int l0 = 0; l0 < LL; l0 += 32) {
        // load P tile 128x32 (transpose into k-major)
#pragma unroll
        for (int i = 0; i < 4; i++) {
            int idx = tid + 256 * i;
            int r  = idx >> 3;
            int c4 = (idx & 7) * 4;
            float4 v = *reinterpret_cast<const float4*>(
                &Pp[(long)r * LL + l0 + c4]);
            Ps[c4 + 0][r] = v.x;
            Ps[c4 + 1][r] = v.y;
            Ps[c4 + 2][r] = v.z;
            Ps[c4 + 3][r] = v.w;
        }
        // load V tile 32x64 (already k-major rows)
#pragma unroll
        for (int i = 0; i < 2; i++) {
            int idx = tid + 256 * i;
            int r  = idx >> 4;
            int c4 = (idx & 15) * 4;
            float4 v = *reinterpret_cast<const float4*>(
                &Vp[(long)(l0 + r) * DD + c4]);
            *reinterpret_cast<float4*>(&Vs[r][c4]) = v;
        }
        __syncthreads();

#pragma unroll
        for (int kk = 0; kk < 32; kk++) {
            float a[8], bb[4];
            float4 t;
            t = *reinterpret_cast<const float4*>(&Ps[kk][ty * 4]);
            a[0]=t.x; a[1]=t.y; a[2]=t.z; a[3]=t.w;
            t = *reinterpret_cast<const float4*>(&Ps[kk][64 + ty * 4]);
            a[4]=t.x; a[5]=t.y; a[6]=t.z; a[7]=t.w;
            t = *reinterpret_cast<const float4*>(&Vs[kk][tx * 4]);
            bb[0]=t.x; bb[1]=t.y; bb[2]=t.z; bb[3]=t.w;
#pragma unroll
            for (int i = 0; i < 8; i++)
#pragma unroll
                for (int j = 0; j < 4; j++)
                    acc[i][j] += a[i] * bb[j];
        }
        __syncthreads();
    }

    const float* rs = rowsum + bh * NN;
#pragma unroll
    for (int i = 0; i < 8; i++) {
        int n = (i < 4) ? (ty * 4 + i) : (64 + ty * 4 + (i - 4));
        float inv = 1.f / rs[n];
        float4 v;
        v.x = acc[i][0] * inv;
        v.y = acc[i][1] * inv;
        v.z = acc[i][2] * inv;
        v.w = acc[i][3] * inv;
        *reinterpret_cast<float4*>(
            &O[(long)b * NN * DD + (long)n * DD + h * DH + tx * 4]) = v;
    }
}

// ---------------- launch ----------------------------------------------------
extern "C" void kernel_launch(void* const* d_in, const int* in_sizes, int n_in,
                              void* d_out, int out_size)
{
    const float* q  = (const float*)d_in[0];
    const float* k  = (const float*)d_in[1];
    const float* v  = (const float*)d_in[2];
    const float* Wq = (const float*)d_in[3];
    const float* Wk = (const float*)d_in[4];
    const float* Wv = (const float*)d_in[5];
    const float* Wo = (const float*)d_in[6];
    float* out = (float*)d_out;

    float *Qp, *Kp, *Vp, *S, *rowpart, *rowsum, *O;
    cudaGetSymbolAddress((void**)&Qp, g_Qp);
    cudaGetSymbolAddress((void**)&Kp, g_Kp);
    cudaGetSymbolAddress((void**)&Vp, g_Vp);
    cudaGetSymbolAddress((void**)&S,  g_S);
    cudaGetSymbolAddress((void**)&rowpart, g_rowpart);
    cudaGetSymbolAddress((void**)&rowsum,  g_rowsum);
    cudaGetSymbolAddress((void**)&O,  g_O);

    const float scale = 0.03125f;   // D^-0.5 = 1/32

    // 1-3: projections  y = x @ W^T  (NT GEMM, K contiguous on both sides)
    gemm_nt<<<dim3(DD/BN, (BB*NN)/BM, 1), 256>>>(
        q, Wq, Qp, DD, DD, DD, DD, 0,0,0,0,0,0, 1, 1.f);
    gemm_nt<<<dim3(DD/BN, (BB*LL)/BM, 1), 256>>>(
        k, Wk, Kp, DD, DD, DD, DD, 0,0,0,0,0,0, 1, 1.f);
    gemm_nt<<<dim3(DD/BN, (BB*LL)/BM, 1), 256>>>(
        v, Wv, Vp, DD, DD, DD, DD, 0,0,0,0,0,0, 1, 1.f);

    // 4: scores S[bh][n][l] = scale * Qh . Kh  (batched over z = b*H + h)
    gemm_nt<<<dim3(LL/BN, NN/BM, BH), 256>>>(
        Qp, Kp, S, DH, DD, DD, LL,
        (long)NN*DD, (long)DH,            // A: +b*N*D, +h*64
        (long)LL*DD, (long)DH,            // B: +b*L*D, +h*64
        (long)HH*NN*LL, (long)NN*LL,      // C: +b*H*N*L, +h*N*L
        HH, scale);

    // 5: inverted softmax (col softmax over n) + row partials
    softmax_inv_kernel<<<dim3(LTILES, BH), 256>>>(S, rowpart);

    // 6: reduce row partials -> rowsum[bh][n]
    rowsum_kernel<<<(BH*NN + 255)/256, 256>>>(rowpart, rowsum);

    // 7: AV with fused L1 normalization, writes O in (b, n, h*64+c) layout
    av_kernel<<<BH, 256>>>(S, Vp, rowsum, O);

    // 8: output projection -> d_out
    gemm_nt<<<dim3(DD/BN, (BB*NN)/BM, 1), 256>>>(
        O, Wo, out, DD, DD, DD, DD, 0,0,0,0,0,0, 1, 1.f);
}

// round 3
// speedup vs baseline: 1.7695x; 1.7695x over previous
#include <cuda_runtime.h>
#include <cuda_bf16.h>
#include <cstdint>

// Problem constants
#define BB 8
#define NN 128
#define LL 4096
#define DD 1024
#define HH 16
#define DH 64
#define BH (BB*HH)          // 128
#define LTILES (LL/32)      // 128

// ---------------- scratch (device globals) ----------------
__device__ float g_Qp[BB*NN*DD];            // 4 MB
__device__ float g_Kp[BB*LL*DD];            // 128 MB
__device__ float g_Vt[BB*DD*LL];            // 128 MB, layout [b][n(1024)][l]
__device__ float g_S [BH*NN*LL];            // 256 MB (scores -> P in place)
__device__ float g_rowpart[BH*LTILES*NN];   // 8 MB
__device__ float g_rowsum[BH*NN];
__device__ float g_O [BB*NN*DD];            // 4 MB

// ---------------- helpers ----------------
__device__ __forceinline__ uint32_t smem_u32(const void* p) {
    uint32_t a;
    asm("{ .reg .u64 t; cvta.to.shared.u64 t, %1; cvt.u32.u64 %0, t; }"
        : "=r"(a) : "l"(p));
    return a;
}

// fp32x4 -> packed hi/lo bf16 planes (u64 each: bytes x,y,z,w order)
__device__ __forceinline__ void pack_hl(float4 v, uint64_t& H, uint64_t& L) {
    uint32_t h01, h23;
    asm("cvt.rn.bf16x2.f32 %0, %1, %2;" : "=r"(h01) : "f"(v.y), "f"(v.x));
    asm("cvt.rn.bf16x2.f32 %0, %1, %2;" : "=r"(h23) : "f"(v.w), "f"(v.z));
    float hx = __uint_as_float(h01 << 16);
    float hy = __uint_as_float(h01 & 0xFFFF0000u);
    float hz = __uint_as_float(h23 << 16);
    float hw = __uint_as_float(h23 & 0xFFFF0000u);
    uint32_t l01, l23;
    asm("cvt.rn.bf16x2.f32 %0, %1, %2;" : "=r"(l01) : "f"(v.y - hy), "f"(v.x - hx));
    asm("cvt.rn.bf16x2.f32 %0, %1, %2;" : "=r"(l23) : "f"(v.w - hw), "f"(v.z - hz));
    H = (uint64_t)h01 | ((uint64_t)h23 << 32);
    L = (uint64_t)l01 | ((uint64_t)l23 << 32);
}

__device__ __forceinline__ void sts64(uint32_t addr, uint64_t v) {
    asm volatile("st.shared.b64 [%0], %1;" :: "r"(addr), "l"(v) : "memory");
}

#define LDSM4(r, a) \
    asm volatile("ldmatrix.sync.aligned.m8n8.x4.shared.b16 {%0,%1,%2,%3}, [%4];" \
        : "=r"((r)[0]), "=r"((r)[1]), "=r"((r)[2]), "=r"((r)[3]) : "r"(a))

#define MMA16816(d, a, b) \
    asm volatile("mma.sync.aligned.m16n8k16.row.col.f32.bf16.bf16.f32 " \
        "{%0,%1,%2,%3}, {%4,%5,%6,%7}, {%8,%9}, {%0,%1,%2,%3};" \
        : "+f"((d)[0]), "+f"((d)[1]), "+f"((d)[2]), "+f"((d)[3]) \
        : "r"((a)[0]), "r"((a)[1]), "r"((a)[2]), "r"((a)[3]), \
          "r"((b)[0]), "r"((b)[1]))

// ---------------- bf16x3 NT GEMM via mma.sync --------------------------------
// C[m,n] = alpha * sum_k A[m,k]*B[n,k]; fp32 in/out.
// Tile 128 x BN, BK = 32 fp32. SMEM rows: 144B pitch, [hi 64B | lo 64B | pad].
// tmode: transposed, smem-staged epilogue (for Vt).
// rowsum: per-row 1/rowsum scaling fused (for AV).
template<int BN>
__global__ void __launch_bounds__(256, 1)
gemm_mma(const float* __restrict__ Ag, const float* __restrict__ Bg,
         float* __restrict__ Cg,
         int K, int lda, int ldb, int ldc,
         long sAb, long sAh, long sBb, long sBh, long sCb, long sCh, int ZH,
         float alpha, const float* __restrict__ rowsum,
         int tmode, long sRow)
{
    constexpr int NWN = BN / 32;          // warps along n
    constexpr int NWM = 8 / NWN;          // warps along m
    constexpr int WM  = 128 / NWM;        // warp m-extent
    constexpr int MT  = WM / 16;          // m16 tiles per warp
    constexpr int ABYTES = 128 * 144;
    constexpr int BBYTES = BN * 144;
    constexpr int STAGE  = ABYTES + BBYTES;
    constexpr int NB = BN / 32;           // B float4 loads per thread

    extern __shared__ char smem[];
    const uint32_t sb = smem_u32(smem);

    const int tid  = threadIdx.x;
    const int wid  = tid >> 5, lane = tid & 31;
    const int wm   = wid % NWM, wn = wid / NWM;

    const int z  = blockIdx.z;
    const int zb = z / ZH, zh = z - zb * ZH;
    const float* A  = Ag + zb * sAb + zh * sAh;
    const float* Bp = Bg + zb * sBb + zh * sBh;
    const int m0 = blockIdx.y * 128;
    const int n0 = blockIdx.x * BN;

    float acc[MT][4][4];
#pragma unroll
    for (int i = 0; i < MT; i++)
#pragma unroll
        for (int j = 0; j < 4; j++)
#pragma unroll
            for (int q = 0; q < 4; q++) acc[i][j][q] = 0.f;

    const int NC = K >> 5;

    float4 ra[4], rb[NB];
    const int lrow = tid >> 3;       // 0..31 base row step
    const int lseg = tid & 7;        // float4 segment within 32-fp32 row

    auto ldg = [&](int c) {
        const int k0 = c << 5;
#pragma unroll
        for (int i = 0; i < 4; i++) {
            int r = lrow + (i << 5);
            ra[i] = *reinterpret_cast<const float4*>(
                &A[(long)(m0 + r) * lda + k0 + (lseg << 2)]);
        }
#pragma unroll
        for (int i = 0; i < NB; i++) {
            int r = lrow + (i << 5);
            rb[i] = *reinterpret_cast<const float4*>(
                &Bp[(long)(n0 + r) * ldb + k0 + (lseg << 2)]);
        }
    };
    auto sts_stage = [&](int st) {
        const uint32_t abase = sb + st * STAGE;
        const uint32_t bbase = abase + ABYTES;
#pragma unroll
        for (int i = 0; i < 4; i++) {
            int r = lrow + (i << 5);
            uint64_t H, L; pack_hl(ra[i], H, L);
            uint32_t o = (uint32_t)(r * 144 + (lseg << 3));
            sts64(abase + o, H);
            sts64(abase + o + 64, L);
        }
#pragma unroll
        for (int i = 0; i < NB; i++) {
            int r = lrow + (i << 5);
            uint64_t H, L; pack_hl(rb[i], H, L);
            uint32_t o = (uint32_t)(r * 144 + (lseg << 3));
            sts64(bbase + o, H);
            sts64(bbase + o + 64, L);
        }
    };
    auto compute = [&](int st) {
        const uint32_t abase = sb + st * STAGE;
        const uint32_t bbase = abase + ABYTES;
        const uint32_t lmo = (uint32_t)(((lane & 15) * 144) + ((lane >> 4) << 4));
#pragma unroll
        for (int ks = 0; ks < 2; ks++) {
            uint32_t ah[MT][4], al[MT][4];
#pragma unroll
            for (int mt = 0; mt < MT; mt++) {
                uint32_t ad = abase + (uint32_t)((wm * WM + mt * 16) * 144 + ks * 32) + lmo;
                LDSM4(ah[mt], ad);
                LDSM4(al[mt], ad + 64);
            }
            uint32_t bhp[4][2], blp[4][2];
#pragma unroll
            for (int j = 0; j < 2; j++) {
                uint32_t bd = bbase + (uint32_t)((wn * 32 + j * 16) * 144 + ks * 32) + lmo;
                uint32_t t[4];
                LDSM4(t, bd);
                bhp[2*j][0] = t[0]; bhp[2*j][1] = t[2];
                bhp[2*j+1][0] = t[1]; bhp[2*j+1][1] = t[3];
                LDSM4(t, bd + 64);
                blp[2*j][0] = t[0]; blp[2*j][1] = t[2];
                blp[2*j+1][0] = t[1]; blp[2*j+1][1] = t[3];
            }
#pragma unroll
            for (int mt = 0; mt < MT; mt++)
#pragma unroll
                for (int nt = 0; nt < 4; nt++) {
                    MMA16816(acc[mt][nt], ah[mt], bhp[nt]);
                    MMA16816(acc[mt][nt], ah[mt], blp[nt]);
                    MMA16816(acc[mt][nt], al[mt], bhp[nt]);
                }
        }
    };

    ldg(0);
    sts_stage(0);
    __syncthreads();

    for (int c = 0; c < NC; c++) {
        if (c + 1 < NC) ldg(c + 1);
        compute(c & 1);
        if (c + 1 < NC) {
            sts_stage((c + 1) & 1);
        }
        __syncthreads();
    }

    if (!tmode) {
        float* Cb = Cg + zb * sCb + zh * sCh;
#pragma unroll
        for (int mt = 0; mt < MT; mt++) {
            int mr = wm * WM + mt * 16 + (lane >> 2);
            float s0 = alpha, s1 = alpha;
            if (rowsum) {
                s0 = alpha / rowsum[(long)z * NN + mr];
                s1 = alpha / rowsum[(long)z * NN + mr + 8];
            }
#pragma unroll
            for (int nt = 0; nt < 4; nt++) {
                int col = n0 + wn * 32 + nt * 8 + (lane & 3) * 2;
                float2 v0, v1;
                v0.x = acc[mt][nt][0] * s0; v0.y = acc[mt][nt][1] * s0;
                v1.x = acc[mt][nt][2] * s1; v1.y = acc[mt][nt][3] * s1;
                *reinterpret_cast<float2*>(&Cb[(long)(m0 + mr) * ldc + col]) = v0;
                *reinterpret_cast<float2*>(&Cb[(long)(m0 + mr + 8) * ldc + col]) = v1;
            }
        }
    } else {
        // transpose via smem, then coalesced stores along l
        float* eps = reinterpret_cast<float*>(smem);
#pragma unroll
        for (int mt = 0; mt < MT; mt++) {
            int mr = wm * WM + mt * 16 + (lane >> 2);
#pragma unroll
            for (int nt = 0; nt < 4; nt++) {
                int cl = wn * 32 + nt * 8 + (lane & 3) * 2;
                eps[(cl + 0) * 132 + mr]     = acc[mt][nt][0] * alpha;
                eps[(cl + 1) * 132 + mr]     = acc[mt][nt][1] * alpha;
                eps[(cl + 0) * 132 + mr + 8] = acc[mt][nt][2] * alpha;
                eps[(cl + 1) * 132 + mr + 8] = acc[mt][nt][3] * alpha;
            }
        }
        __syncthreads();
        const int b  = m0 >> 12;
        const int l0 = m0 & 4095;
        for (int i = tid; i < BN * 32; i += 256) {
            int cc = i >> 5, j = i & 31;
            float4 v = *reinterpret_cast<const float4*>(&eps[cc * 132 + j * 4]);
            *reinterpret_cast<float4*>(
                &Cg[(long)b * sRow + (long)(n0 + cc) * ldc + l0 + j * 4]) = v;
        }
    }
}

// ---------------- inverted softmax (over query axis n) ----------------------
__global__ void __launch_bounds__(256)
softmax_inv_kernel(float* __restrict__ S, float* __restrict__ rowpart)
{
    const int bh   = blockIdx.y;
    const int lane = threadIdx.x & 31;
    const int g    = threadIdx.x >> 5;
    const int l    = blockIdx.x * 32 + lane;

    float* Sp = S + (long)bh * NN * LL;

    float s[16];
#pragma unroll
    for (int r = 0; r < 16; r++)
        s[r] = Sp[(long)(g + r * 8) * LL + l];

    __shared__ float red[8][32];

    float m = s[0];
#pragma unroll
    for (int r = 1; r < 16; r++) m = fmaxf(m, s[r]);
    red[g][lane] = m;
    __syncthreads();
    float cm = red[0][lane];
#pragma unroll
    for (int i = 1; i < 8; i++) cm = fmaxf(cm, red[i][lane]);
    __syncthreads();

    float sum = 0.f;
#pragma unroll
    for (int r = 0; r < 16; r++) {
        s[r] = __expf(s[r] - cm);
        sum += s[r];
    }
    red[g][lane] = sum;
    __syncthreads();
    float cs = 0.f;
#pragma unroll
    for (int i = 0; i < 8; i++) cs += red[i][lane];
    float inv = 1.f / cs;

#pragma unroll
    for (int r = 0; r < 16; r++) {
        float p = s[r] * inv;
        s[r] = p;
        Sp[(long)(g + r * 8) * LL + l] = p;
    }
#pragma unroll
    for (int r = 0; r < 16; r++) {
        float v = s[r];
#pragma unroll
        for (int off = 16; off > 0; off >>= 1)
            v += __shfl_xor_sync(0xffffffffu, v, off);
        if (lane == 0)
            rowpart[((long)bh * LTILES + blockIdx.x) * NN + (g + r * 8)] = v;
    }
}

__global__ void rowsum_kernel(const float* __restrict__ rowpart,
                              float* __restrict__ rowsum)
{
    int idx = blockIdx.x * blockDim.x + threadIdx.x;
    if (idx >= BH * NN) return;
    int bh = idx >> 7;
    int n  = idx & 127;
    const float* p = rowpart + (long)bh * LTILES * NN + n;
    float s = 0.f;
#pragma unroll 8
    for (int t = 0; t < LTILES; t++) s += p[(long)t * NN];
    rowsum[idx] = s;
}

// ---------------- launch ----------------------------------------------------
extern "C" void kernel_launch(void* const* d_in, const int* in_sizes, int n_in,
                              void* d_out, int out_size)
{
    const float* q  = (const float*)d_in[0];
    const float* k  = (const float*)d_in[1];
    const float* v  = (const float*)d_in[2];
    const float* Wq = (const float*)d_in[3];
    const float* Wk = (const float*)d_in[4];
    const float* Wv = (const float*)d_in[5];
    const float* Wo = (const float*)d_in[6];
    float* out = (float*)d_out;

    float *Qp, *Kp, *Vt, *S, *rowpart, *rs, *O;
    cudaGetSymbolAddress((void**)&Qp, g_Qp);
    cudaGetSymbolAddress((void**)&Kp, g_Kp);
    cudaGetSymbolAddress((void**)&Vt, g_Vt);
    cudaGetSymbolAddress((void**)&S,  g_S);
    cudaGetSymbolAddress((void**)&rowpart, g_rowpart);
    cudaGetSymbolAddress((void**)&rs, g_rowsum);
    cudaGetSymbolAddress((void**)&O,  g_O);

    const int SZ128 = 2 * (128 * 144 + 128 * 144);   // 73728
    const int SZ64  = 2 * (128 * 144 + 64 * 144);    // 55296
    cudaFuncSetAttribute((const void*)gemm_mma<128>,
                         cudaFuncAttributeMaxDynamicSharedMemorySize, SZ128);
    cudaFuncSetAttribute((const void*)gemm_mma<64>,
                         cudaFuncAttributeMaxDynamicSharedMemorySize, SZ64);

    const float scale = 0.03125f;   // D^-0.5

    // Q projection: [1024 x 1024] @ Wq^T
    gemm_mma<128><<<dim3(DD/128, (BB*NN)/128, 1), 256, SZ128>>>(
        q, Wq, Qp, DD, DD, DD, DD, 0,0,0,0,0,0, 1, 1.f, nullptr, 0, 0);
    // K projection: [32768 x 1024]
    gemm_mma<128><<<dim3(DD/128, (BB*LL)/128, 1), 256, SZ128>>>(
        k, Wk, Kp, DD, DD, DD, DD, 0,0,0,0,0,0, 1, 1.f, nullptr, 0, 0);
    // V projection -> transposed: Vt[b][n][l]
    gemm_mma<128><<<dim3(DD/128, (BB*LL)/128, 1), 256, SZ128>>>(
        v, Wv, Vt, DD, DD, DD, LL, 0,0,0,0,0,0, 1, 1.f, nullptr,
        1, (long)DD * LL);

    // Scores: S[bh][n][l] = scale * Qh . Kh   (z = b*16 + h)
    gemm_mma<128><<<dim3(LL/128, 1, BH), 256, SZ128>>>(
        Qp, Kp, S, DH, DD, DD, LL,
        (long)NN*DD, (long)DH,
        (long)LL*DD, (long)DH,
        (long)HH*NN*LL, (long)NN*LL,
        HH, scale, nullptr, 0, 0);

    softmax_inv_kernel<<<dim3(LTILES, BH), 256>>>(S, rowpart);
    rowsum_kernel<<<(BH*NN + 255)/256, 256>>>(rowpart, rs);

    // AV: O[b][n][h*64+c] = (P . Vt) / rowsum   (K = 4096, N = 64)
    gemm_mma<64><<<dim3(1, 1, BH), 256, SZ64>>>(
        S, Vt, O, LL, LL, LL, DD,
        (long)HH*NN*LL, (long)NN*LL,
        (long)HH*DH*LL, (long)DH*LL,
        (long)NN*DD, (long)DH,
        HH, 1.f, rs, 0, 0);

    // Output projection
    gemm_mma<128><<<dim3(DD/128, (BB*NN)/128, 1), 256, SZ128>>>(
        O, Wo, out, DD, DD, DD, DD, 0,0,0,0,0,0, 1, 1.f, nullptr, 0, 0);
}

// round 4
// speedup vs baseline: 2.2181x; 1.2535x over previous
#include <cuda_runtime.h>
#include <cuda_bf16.h>
#include <cstdint>

// Problem constants
#define BB 8
#define NN 128
#define LL 4096
#define DD 1024
#define HH 16
#define DH 64
#define BH (BB*HH)          // 128

// ---------------- scratch (device globals) ----------------
__device__ float g_Qp[BB*NN*DD];            // 4 MB
__device__ float g_Kp[BB*LL*DD];            // 128 MB
__device__ float g_Vp[BB*LL*DD];            // 128 MB
__device__ float g_O [BB*NN*DD];            // 4 MB

// ---------------- helpers ----------------
__device__ __forceinline__ uint32_t smem_u32(const void* p) {
    uint32_t a;
    asm("{ .reg .u64 t; cvta.to.shared.u64 t, %1; cvt.u32.u64 %0, t; }"
        : "=r"(a) : "l"(p));
    return a;
}

// pack two floats into bf16x2 (x -> low, y -> high)
__device__ __forceinline__ uint32_t pk2(float x, float y) {
    uint32_t r;
    asm("cvt.rn.bf16x2.f32 %0, %1, %2;" : "=r"(r) : "f"(y), "f"(x));
    return r;
}
// residual pack: lo = (x,y) - bf16(hi packed)
__device__ __forceinline__ uint32_t pk2lo(float x, float y, uint32_t h) {
    float hx = __uint_as_float(h << 16);
    float hy = __uint_as_float(h & 0xFFFF0000u);
    uint32_t r;
    asm("cvt.rn.bf16x2.f32 %0, %1, %2;" : "=r"(r) : "f"(y - hy), "f"(x - hx));
    return r;
}

// fp32x4 -> packed hi/lo bf16 planes (u64 each)
__device__ __forceinline__ void pack_hl(float4 v, uint64_t& H, uint64_t& L) {
    uint32_t h01 = pk2(v.x, v.y);
    uint32_t h23 = pk2(v.z, v.w);
    uint32_t l01 = pk2lo(v.x, v.y, h01);
    uint32_t l23 = pk2lo(v.z, v.w, h23);
    H = (uint64_t)h01 | ((uint64_t)h23 << 32);
    L = (uint64_t)l01 | ((uint64_t)l23 << 32);
}

__device__ __forceinline__ void sts64(uint32_t addr, uint64_t v) {
    asm volatile("st.shared.b64 [%0], %1;" :: "r"(addr), "l"(v) : "memory");
}
__device__ __forceinline__ void sts32(uint32_t addr, uint32_t v) {
    asm volatile("st.shared.b32 [%0], %1;" :: "r"(addr), "r"(v) : "memory");
}
__device__ __forceinline__ void cp16(uint32_t s, const void* g) {
    asm volatile("cp.async.cg.shared.global [%0], [%1], 16;" :: "r"(s), "l"(g));
}
#define CP_COMMIT() asm volatile("cp.async.commit_group;" ::: "memory")
#define CP_WAIT0()  asm volatile("cp.async.wait_group 0;" ::: "memory")

#define LDSM4(r, a) \
    asm volatile("ldmatrix.sync.aligned.m8n8.x4.shared.b16 {%0,%1,%2,%3}, [%4];" \
        : "=r"((r)[0]), "=r"((r)[1]), "=r"((r)[2]), "=r"((r)[3]) : "r"(a))
#define LDSM4T(r, a) \
    asm volatile("ldmatrix.sync.aligned.m8n8.x4.trans.shared.b16 {%0,%1,%2,%3}, [%4];" \
        : "=r"((r)[0]), "=r"((r)[1]), "=r"((r)[2]), "=r"((r)[3]) : "r"(a))

#define MMA16816(d, a, b) \
    asm volatile("mma.sync.aligned.m16n8k16.row.col.f32.bf16.bf16.f32 " \
        "{%0,%1,%2,%3}, {%4,%5,%6,%7}, {%8,%9}, {%0,%1,%2,%3};" \
        : "+f"((d)[0]), "+f"((d)[1]), "+f"((d)[2]), "+f"((d)[3]) \
        : "r"((a)[0]), "r"((a)[1]), "r"((a)[2]), "r"((a)[3]), \
          "r"((b)[0]), "r"((b)[1]))

// ---------------- bf16x3 NT GEMM (projections): C = A @ B^T ------------------
// Tile 128 x 64, BK = 32 fp32. 8 warps as 4(m) x 2(n), warp tile 32x32.
__global__ void __launch_bounds__(256, 2)
gemm_mma(const float* __restrict__ A, const float* __restrict__ Bp,
         float* __restrict__ Cg, int K, int lda, int ldb, int ldc, float alpha)
{
    constexpr int BN = 64;
    constexpr int ABYTES = 128 * 144;
    constexpr int BBYTES = BN * 144;
    constexpr int STAGE  = ABYTES + BBYTES;

    extern __shared__ char smem[];
    const uint32_t sb = smem_u32(smem);

    const int tid  = threadIdx.x;
    const int wid  = tid >> 5, lane = tid & 31;
    const int wm   = wid & 3, wn = wid >> 2;          // 4 x 2

    const int m0 = blockIdx.y * 128;
    const int n0 = blockIdx.x * BN;

    float acc[2][4][4];
#pragma unroll
    for (int i = 0; i < 2; i++)
#pragma unroll
        for (int j = 0; j < 4; j++)
#pragma unroll
            for (int q = 0; q < 4; q++) acc[i][j][q] = 0.f;

    const int NC = K >> 5;
    float4 ra[4], rb[2];
    const int lrow = tid >> 3;
    const int lseg = tid & 7;

    auto ldg = [&](int c) {
        const int k0 = c << 5;
#pragma unroll
        for (int i = 0; i < 4; i++)
            ra[i] = *reinterpret_cast<const float4*>(
                &A[(long)(m0 + lrow + (i << 5)) * lda + k0 + (lseg << 2)]);
#pragma unroll
        for (int i = 0; i < 2; i++)
            rb[i] = *reinterpret_cast<const float4*>(
                &Bp[(long)(n0 + lrow + (i << 5)) * ldb + k0 + (lseg << 2)]);
    };
    auto sts_stage = [&](int st) {
        const uint32_t abase = sb + st * STAGE;
        const uint32_t bbase = abase + ABYTES;
#pragma unroll
        for (int i = 0; i < 4; i++) {
            uint64_t H, L; pack_hl(ra[i], H, L);
            uint32_t o = (uint32_t)((lrow + (i << 5)) * 144 + (lseg << 3));
            sts64(abase + o, H); sts64(abase + o + 64, L);
        }
#pragma unroll
        for (int i = 0; i < 2; i++) {
            uint64_t H, L; pack_hl(rb[i], H, L);
            uint32_t o = (uint32_t)((lrow + (i << 5)) * 144 + (lseg << 3));
            sts64(bbase + o, H); sts64(bbase + o + 64, L);
        }
    };
    auto compute = [&](int st) {
        const uint32_t abase = sb + st * STAGE;
        const uint32_t bbase = abase + ABYTES;
        const uint32_t lmo = (uint32_t)(((lane & 15) * 144) + ((lane >> 4) << 4));
#pragma unroll
        for (int ks = 0; ks < 2; ks++) {
            uint32_t ah[2][4], al[2][4];
#pragma unroll
            for (int mt = 0; mt < 2; mt++) {
                uint32_t ad = abase + (uint32_t)((wm * 32 + mt * 16) * 144 + ks * 32) + lmo;
                LDSM4(ah[mt], ad);
                LDSM4(al[mt], ad + 64);
            }
            uint32_t bhp[4][2], blp[4][2];
#pragma unroll
            for (int j = 0; j < 2; j++) {
                uint32_t bd = bbase + (uint32_t)((wn * 32 + j * 16) * 144 + ks * 32) + lmo;
                uint32_t t[4];
                LDSM4(t, bd);
                bhp[2*j][0] = t[0]; bhp[2*j][1] = t[2];
                bhp[2*j+1][0] = t[1]; bhp[2*j+1][1] = t[3];
                LDSM4(t, bd + 64);
                blp[2*j][0] = t[0]; blp[2*j][1] = t[2];
                blp[2*j+1][0] = t[1]; blp[2*j+1][1] = t[3];
            }
#pragma unroll
            for (int mt = 0; mt < 2; mt++)
#pragma unroll
                for (int nt = 0; nt < 4; nt++) {
                    MMA16816(acc[mt][nt], ah[mt], bhp[nt]);
                    MMA16816(acc[mt][nt], ah[mt], blp[nt]);
                    MMA16816(acc[mt][nt], al[mt], bhp[nt]);
                }
        }
    };

    ldg(0);
    sts_stage(0);
    __syncthreads();

    for (int c = 0; c < NC; c++) {
        if (c + 1 < NC) ldg(c + 1);
        compute(c & 1);
        if (c + 1 < NC) sts_stage((c + 1) & 1);
        __syncthreads();
    }

#pragma unroll
    for (int mt = 0; mt < 2; mt++) {
        int mr = m0 + wm * 32 + mt * 16 + (lane >> 2);
#pragma unroll
        for (int nt = 0; nt < 4; nt++) {
            int col = n0 + wn * 32 + nt * 8 + (lane & 3) * 2;
            float2 v0, v1;
            v0.x = acc[mt][nt][0] * alpha; v0.y = acc[mt][nt][1] * alpha;
            v1.x = acc[mt][nt][2] * alpha; v1.y = acc[mt][nt][3] * alpha;
            *reinterpret_cast<float2*>(&Cg[(long)mr * ldc + col]) = v0;
            *reinterpret_cast<float2*>(&Cg[(long)(mr + 8) * ldc + col]) = v1;
        }
    }
}

// ---------------- fused attention -------------------------------------------
// One CTA per (b,h). S = Q@K^T chunkwise; exact column softmax over n=128;
// P@[V | ones] accumulated; epilogue divides by rowsum (ones column).
#define FPK 144            // Q/K plane pitch (64 bf16 + pad)
#define FPV 176            // V plane pitch (72 bf16 + pad)
#define QHI_O 0
#define QLO_O 18432
#define KHI_O 36864
#define KLO_O 55296
#define VHI_O 73728
#define VLO_O 96256
#define STK_O 118784
#define STV_O 151552
#define CST_O 184320
#define FUSED_SMEM (CST_O + 9*128*4)   // 188928

__global__ void __launch_bounds__(256, 1)
fused_attn(const float* __restrict__ Qp, const float* __restrict__ Kp,
           const float* __restrict__ Vp, float* __restrict__ O)
{
    extern __shared__ char smem[];
    const uint32_t sb = smem_u32(smem);
    float* cst = reinterpret_cast<float*>(smem + CST_O);

    const int tid = threadIdx.x, wid = tid >> 5, lane = tid & 31;
    const int bh = blockIdx.x, b = bh >> 4, h = bh & 15;
    const float* Qg = Qp + (long)b * NN * DD + h * DH;
    const float* Kg = Kp + (long)b * LL * DD + h * DH;
    const float* Vg = Vp + (long)b * LL * DD + h * DH;

    const uint32_t QHI = sb + QHI_O, QLO = sb + QLO_O;
    const uint32_t KHI = sb + KHI_O, KLO = sb + KLO_O;
    const uint32_t VHI = sb + VHI_O, VLO = sb + VLO_O;
    const uint32_t STK = sb + STK_O, STV = sb + STV_O;

    // init V ones columns (64..71) + zero pad (72..79), both planes
    for (int r = tid; r < 128; r += 256) {
        uint32_t ro = (uint32_t)r * FPV;
#pragma unroll
        for (int cb = 0; cb < 4; cb++) {
            sts32(VHI + ro + 128 + cb * 4, 0x3F803F80u);  // bf16 1.0 x2
            sts32(VLO + ro + 128 + cb * 4, 0u);
            sts32(VHI + ro + 144 + cb * 4, 0u);           // pad zeros
            sts32(VLO + ro + 144 + cb * 4, 0u);
        }
    }

    // load Q (scaled by D^-0.5) into bf16 hi/lo planes
    const float SCALE = 0.03125f;
#pragma unroll
    for (int i = 0; i < 8; i++) {
        int idx = tid + i * 256;
        int r = idx >> 4, s = idx & 15;
        float4 v = *reinterpret_cast<const float4*>(&Qg[(long)r * DD + s * 4]);
        v.x *= SCALE; v.y *= SCALE; v.z *= SCALE; v.w *= SCALE;
        uint64_t H, L; pack_hl(v, H, L);
        sts64(QHI + r * FPK + s * 8, H);
        sts64(QLO + r * FPK + s * 8, L);
    }

    auto cpasync_chunk = [&](int c) {
        long l0 = (long)c * 128;
#pragma unroll
        for (int i = 0; i < 8; i++) {
            int idx = tid + i * 256;
            int r = idx >> 4, s = idx & 15;
            cp16(STK + (uint32_t)(r * 256 + s * 16), &Kg[(l0 + r) * DD + s * 4]);
            cp16(STV + (uint32_t)(r * 256 + s * 16), &Vg[(l0 + r) * DD + s * 4]);
        }
        CP_COMMIT();
    };
    auto cvt_chunk = [&]() {
        const float4* stk = reinterpret_cast<const float4*>(smem + STK_O);
        const float4* stv = reinterpret_cast<const float4*>(smem + STV_O);
#pragma unroll
        for (int i = 0; i < 8; i++) {
            int idx = tid + i * 256;
            int r = idx >> 4, s = idx & 15;
            uint64_t H, L;
            pack_hl(stk[r * 16 + s], H, L);
            sts64(KHI + r * FPK + s * 8, H);
            sts64(KLO + r * FPK + s * 8, L);
            pack_hl(stv[r * 16 + s], H, L);
            sts64(VHI + r * FPV + s * 8, H);
            sts64(VLO + r * FPV + s * 8, L);
        }
    };

    float acc2[9][4];
#pragma unroll
    for (int i = 0; i < 9; i++)
#pragma unroll
        for (int j = 0; j < 4; j++) acc2[i][j] = 0.f;

    const int mrow = wid * 16;
    const uint32_t lqk = (uint32_t)((lane & 15) * FPK + ((lane >> 4) << 4));
    const uint32_t lv  = (uint32_t)((lane & 15) * FPV + ((lane >> 4) << 4));

    cpasync_chunk(0);
    CP_WAIT0();
    __syncthreads();
    cvt_chunk();
    __syncthreads();

    for (int c = 0; c < 32; c++) {
        if (c + 1 < 32) cpasync_chunk(c + 1);

        // ---- MMA1: S fragments acc1[nt 0..15][4], rows mrow..mrow+15
        float acc1[16][4];
#pragma unroll
        for (int i = 0; i < 16; i++)
#pragma unroll
            for (int j = 0; j < 4; j++) acc1[i][j] = 0.f;

#pragma unroll
        for (int ks = 0; ks < 4; ks++) {
            uint32_t ah[4], al[4];
            LDSM4(ah, QHI + (uint32_t)(mrow * FPK + ks * 32) + lqk);
            LDSM4(al, QLO + (uint32_t)(mrow * FPK + ks * 32) + lqk);
#pragma unroll
            for (int nt2 = 0; nt2 < 8; nt2++) {
                uint32_t th[4], tl[4];
                LDSM4(th, KHI + (uint32_t)(nt2 * 16 * FPK + ks * 32) + lqk);
                LDSM4(tl, KLO + (uint32_t)(nt2 * 16 * FPK + ks * 32) + lqk);
                uint32_t b0h[2] = {th[0], th[2]}, b1h[2] = {th[1], th[3]};
                uint32_t b0l[2] = {tl[0], tl[2]}, b1l[2] = {tl[1], tl[3]};
                MMA16816(acc1[2*nt2],   ah, b0h);
                MMA16816(acc1[2*nt2],   ah, b0l);
                MMA16816(acc1[2*nt2],   al, b0h);
                MMA16816(acc1[2*nt2+1], ah, b1h);
                MMA16816(acc1[2*nt2+1], ah, b1l);
                MMA16816(acc1[2*nt2+1], al, b1h);
            }
        }

        // ---- column max over n (rows): intra-thread, shuffle, cross-warp smem
#pragma unroll
        for (int nt = 0; nt < 16; nt++) {
            float m0 = fmaxf(acc1[nt][0], acc1[nt][2]);
            float m1 = fmaxf(acc1[nt][1], acc1[nt][3]);
            m0 = fmaxf(m0, __shfl_xor_sync(0xffffffffu, m0, 4));
            m0 = fmaxf(m0, __shfl_xor_sync(0xffffffffu, m0, 8));
            m0 = fmaxf(m0, __shfl_xor_sync(0xffffffffu, m0, 16));
            m1 = fmaxf(m1, __shfl_xor_sync(0xffffffffu, m1, 4));
            m1 = fmaxf(m1, __shfl_xor_sync(0xffffffffu, m1, 8));
            m1 = fmaxf(m1, __shfl_xor_sync(0xffffffffu, m1, 16));
            if (lane < 4) {
                cst[wid * 128 + nt * 8 + lane * 2]     = m0;
                cst[wid * 128 + nt * 8 + lane * 2 + 1] = m1;
            }
        }
        __syncthreads();
        if (tid < 128) {
            float g = cst[tid];
#pragma unroll
            for (int w = 1; w < 8; w++) g = fmaxf(g, cst[w * 128 + tid]);
            cst[1024 + tid] = g;
        }
        __syncthreads();

        // ---- exp + column sum
#pragma unroll
        for (int nt = 0; nt < 16; nt++) {
            float2 gm = *reinterpret_cast<const float2*>(
                &cst[1024 + nt * 8 + (lane & 3) * 2]);
            acc1[nt][0] = __expf(acc1[nt][0] - gm.x);
            acc1[nt][1] = __expf(acc1[nt][1] - gm.y);
            acc1[nt][2] = __expf(acc1[nt][2] - gm.x);
            acc1[nt][3] = __expf(acc1[nt][3] - gm.y);
            float s0 = acc1[nt][0] + acc1[nt][2];
            float s1 = acc1[nt][1] + acc1[nt][3];
            s0 += __shfl_xor_sync(0xffffffffu, s0, 4);
            s0 += __shfl_xor_sync(0xffffffffu, s0, 8);
            s0 += __shfl_xor_sync(0xffffffffu, s0, 16);
            s1 += __shfl_xor_sync(0xffffffffu, s1, 4);
            s1 += __shfl_xor_sync(0xffffffffu, s1, 8);
            s1 += __shfl_xor_sync(0xffffffffu, s1, 16);
            if (lane < 4) {
                cst[wid * 128 + nt * 8 + lane * 2]     = s0;
                cst[wid * 128 + nt * 8 + lane * 2 + 1] = s1;
            }
        }
        __syncthreads();
        if (tid < 128) {
            float s = 0.f;
#pragma unroll
            for (int w = 0; w < 8; w++) s += cst[w * 128 + tid];
            cst[1024 + tid] = 1.f / s;
        }
        __syncthreads();
#pragma unroll
        for (int nt = 0; nt < 16; nt++) {
            float2 iv = *reinterpret_cast<const float2*>(
                &cst[1024 + nt * 8 + (lane & 3) * 2]);
            acc1[nt][0] *= iv.x; acc1[nt][1] *= iv.y;
            acc1[nt][2] *= iv.x; acc1[nt][3] *= iv.y;
        }

        // ---- MMA2: acc2 += P @ [V | ones]  (A = acc1 fragments, registers)
#pragma unroll
        for (int ks2 = 0; ks2 < 8; ks2++) {
            const float* p0 = acc1[2*ks2];
            const float* p1 = acc1[2*ks2+1];
            uint32_t pah[4], pal[4];
            pah[0] = pk2(p0[0], p0[1]); pal[0] = pk2lo(p0[0], p0[1], pah[0]);
            pah[1] = pk2(p0[2], p0[3]); pal[1] = pk2lo(p0[2], p0[3], pah[1]);
            pah[2] = pk2(p1[0], p1[1]); pal[2] = pk2lo(p1[0], p1[1], pah[2]);
            pah[3] = pk2(p1[2], p1[3]); pal[3] = pk2lo(p1[2], p1[3], pah[3]);
#pragma unroll
            for (int nt2 = 0; nt2 < 5; nt2++) {
                uint32_t th[4], tl[4];
                LDSM4T(th, VHI + (uint32_t)(ks2 * 16 * FPV + nt2 * 32) + lv);
                LDSM4T(tl, VLO + (uint32_t)(ks2 * 16 * FPV + nt2 * 32) + lv);
                uint32_t b0h[2] = {th[0], th[1]}, b0l[2] = {tl[0], tl[1]};
                MMA16816(acc2[2*nt2], pah, b0h);
                MMA16816(acc2[2*nt2], pah, b0l);
                MMA16816(acc2[2*nt2], pal, b0h);
                if (nt2 < 4) {
                    uint32_t b1h[2] = {th[2], th[3]}, b1l[2] = {tl[2], tl[3]};
                    MMA16816(acc2[2*nt2+1], pah, b1h);
                    MMA16816(acc2[2*nt2+1], pah, b1l);
                    MMA16816(acc2[2*nt2+1], pal, b1h);
                }
            }
        }

        if (c + 1 < 32) CP_WAIT0();
        __syncthreads();             // all reads of K/V planes done; staging landed
        if (c + 1 < 32) {
            cvt_chunk();
            __syncthreads();
        }
    }

    // ---- epilogue: divide by rowsum (ones column = acc2[8][0]/[2]), store O
    float rs0 = __shfl_sync(0xffffffffu, acc2[8][0], lane & ~3);
    float rs2 = __shfl_sync(0xffffffffu, acc2[8][2], lane & ~3);
    float i0 = 1.f / rs0, i2 = 1.f / rs2;
    int r0 = mrow + (lane >> 2);
    float* Ob = O + (long)b * NN * DD + h * DH;
#pragma unroll
    for (int nt = 0; nt < 8; nt++) {
        int cc = nt * 8 + (lane & 3) * 2;
        float2 v0, v1;
        v0.x = acc2[nt][0] * i0; v0.y = acc2[nt][1] * i0;
        v1.x = acc2[nt][2] * i2; v1.y = acc2[nt][3] * i2;
        *reinterpret_cast<float2*>(&Ob[(long)r0 * DD + cc]) = v0;
        *reinterpret_cast<float2*>(&Ob[(long)(r0 + 8) * DD + cc]) = v1;
    }
}

// ---------------- launch ----------------------------------------------------
extern "C" void kernel_launch(void* const* d_in, const int* in_sizes, int n_in,
                              void* d_out, int out_size)
{
    const float* q  = (const float*)d_in[0];
    const float* k  = (const float*)d_in[1];
    const float* v  = (const float*)d_in[2];
    const float* Wq = (const float*)d_in[3];
    const float* Wk = (const float*)d_in[4];
    const float* Wv = (const float*)d_in[5];
    const float* Wo = (const float*)d_in[6];
    float* out = (float*)d_out;

    float *Qp, *Kp, *Vp, *O;
    cudaGetSymbolAddress((void**)&Qp, g_Qp);
    cudaGetSymbolAddress((void**)&Kp, g_Kp);
    cudaGetSymbolAddress((void**)&Vp, g_Vp);
    cudaGetSymbolAddress((void**)&O,  g_O);

    const int SZG = 2 * (128 * 144 + 64 * 144);   // 55296
    cudaFuncSetAttribute((const void*)gemm_mma,
                         cudaFuncAttributeMaxDynamicSharedMemorySize, SZG);
    cudaFuncSetAttribute((const void*)fused_attn,
                         cudaFuncAttributeMaxDynamicSharedMemorySize, FUSED_SMEM);

    // projections
    gemm_mma<<<dim3(DD/64, (BB*NN)/128), 256, SZG>>>(
        q, Wq, Qp, DD, DD, DD, DD, 1.f);
    gemm_mma<<<dim3(DD/64, (BB*LL)/128), 256, SZG>>>(
        k, Wk, Kp, DD, DD, DD, DD, 1.f);
    gemm_mma<<<dim3(DD/64, (BB*LL)/128), 256, SZG>>>(
        v, Wv, Vp, DD, DD, DD, DD, 1.f);

    // fused: scores + inverted softmax + L1 renorm + AV
    fused_attn<<<BH, 256, FUSED_SMEM>>>(Qp, Kp, Vp, O);

    // output projection
    gemm_mma<<<dim3(DD/64, (BB*NN)/128), 256, SZG>>>(
        O, Wo, out, DD, DD, DD, DD, 1.f);
}